// round 10
// baseline (speedup 1.0000x reference)
#include <cuda_runtime.h>
#include <cuda_bf16.h>
#include <math.h>

// Problem constants
#define DD      256
#define KCODES  8192
#define BATCH   8
#define HW      1024
#define NTOK    8192

// Output layout (flattened return tuple, in order)
#define OUT_Q     0
#define OUT_LOSS  2097152
#define OUT_PERP  2097153
#define OUT_IDX   2097154
#define OUT_DW    2105346
#define OUT_CS    4202498

// GEMM config: C[8192 tok, 8192 codes] = A[.,768] * B[.,768]^T  (bf16x3 split)
#define KTOT    768
#define MTILE   128
#define NTILE   128
#define KS      64
#define NSTAGES 12                    // 768/64 per n-block
#define GSTAGES 24                    // 2 n-blocks per CTA, continuous pipeline
#define NPIPE   3                     // cp.async pipeline depth
#define NSPLITS (KCODES / NTILE)      // 64
#define ABYTES  16384                 // per-stage A buffer (128 x 128B)
#define BBYTES  16384                 // per-stage B buffer
#define SM_RED  (NPIPE * (ABYTES + BBYTES))    // 98304: sred after tiles
#define SMEM_DYN (SM_RED + 4096)               // 100KB/CTA -> 2 CTAs/SM

typedef unsigned long long ull;
typedef unsigned int uint;

// ---------------- device scratch (no allocation allowed) --------------------
__device__ __nv_bfloat16 g_A[NTOK   * KTOT];  // [tok ][xh(256)|xh(256)|xl(256)]
__device__ __nv_bfloat16 g_B[KCODES * KTOT];  // [code][eh(256)|el(256)|eh(256)]
__device__ float  g_e2[KCODES];
__device__ float  g_sx2[NTOK];
__device__ ull    g_top1[NTOK * NSPLITS];     // [token][split]  (coalesced merge)
__device__ ull    g_top2[NTOK * NSPLITS];
__device__ int    g_idx[NTOK];
__device__ double g_loss;

// ---------------- PTX helpers (all plain-sm_100 legal) ----------------------
__device__ __forceinline__ uint smem_u32(const void* p) {
    uint a;
    asm("{ .reg .u64 t; cvta.to.shared.u64 t, %1; cvt.u32.u64 %0, t; }"
        : "=r"(a) : "l"(p));
    return a;
}
#define CP16(dst, src) \
    asm volatile("cp.async.cg.shared.global [%0], [%1], 16;" :: "r"(dst), "l"(src))
#define CP_COMMIT() asm volatile("cp.async.commit_group;")
#define CP_WAIT(n)  asm volatile("cp.async.wait_group %0;" :: "n"(n))

#define LDSM4(r0, r1, r2, r3, a) \
    asm volatile("ldmatrix.sync.aligned.m8n8.x4.shared.b16 {%0,%1,%2,%3}, [%4];" \
        : "=r"(r0), "=r"(r1), "=r"(r2), "=r"(r3) : "r"(a))

#define MMA16816(c, a, b) \
    asm volatile("mma.sync.aligned.m16n8k16.row.col.f32.bf16.bf16.f32 " \
        "{%0,%1,%2,%3}, {%4,%5,%6,%7}, {%8,%9}, {%0,%1,%2,%3};" \
        : "+f"((c)[0]), "+f"((c)[1]), "+f"((c)[2]), "+f"((c)[3]) \
        : "r"((a)[0]), "r"((a)[1]), "r"((a)[2]), "r"((a)[3]), \
          "r"((b)[0]), "r"((b)[1]))

__device__ __forceinline__ ull umax(ull a, ull b) { return a > b ? a : b; }
__device__ __forceinline__ ull umin(ull a, ull b) { return a < b ? a : b; }

// ---------------------------------------------------------------------------
// K_prep (fused init + norms + transpose/split, vectorized bf16 stores):
//   Blocks 0..255:   z -> g_A (32 tokens each) + g_sx2
//   Blocks 256..511: E -> g_B (32 codes each)  + g_e2
// ---------------------------------------------------------------------------
__global__ void k_prep(const float* __restrict__ z, const float* __restrict__ E,
                       float* __restrict__ out) {
    __shared__ float st[32 * 264];
    const int tid = threadIdx.x;
    const bool isB = blockIdx.x >= 256;
    const int n0 = (isB ? (blockIdx.x - 256) : blockIdx.x) * 32;

    // zero dw + cluster_size (2105344 floats = 1052672 float2, 8B-aligned)
    {
        const float2 z2 = make_float2(0.0f, 0.0f);
        float2* dst2 = (float2*)(out + OUT_DW);
        for (int i = blockIdx.x * 256 + tid; i < 1052672; i += 512 * 256)
            dst2[i] = z2;
        if (blockIdx.x == 0 && tid == 0) g_loss = 0.0;
    }

    // load 32 rows x 256 dims into smem (transposed)
    for (int i = tid; i < 32 * 256; i += 256) {
        int k = i >> 5, nl = i & 31;
        float v;
        if (isB) v = E[k * KCODES + n0 + nl];
        else {
            int b = n0 >> 10, hw0 = n0 & 1023;
            v = z[(b * DD + k) * HW + hw0 + nl];
        }
        st[nl * 264 + k] = v;
    }
    __syncthreads();

    // norms: one thread per row, sequential fp32 over d (bit-identical path)
    if (tid < 32) {
        float s = 0.0f;
        #pragma unroll 8
        for (int d = 0; d < DD; d++) { float v = st[tid * 264 + d]; s += v * v; }
        if (isB) g_e2[n0 + tid] = s;
        else     g_sx2[n0 + tid] = s;
    }

    // bf16 hi/lo split, packed stores:  A row [xh|xh|xl],  B row [eh|el|eh]
    __nv_bfloat16* dst = isB ? g_B : g_A;
    const int nl = tid >> 3;
    const int jb = (tid & 7) * 32;
    __nv_bfloat16* rowp = dst + (ull)(n0 + nl) * KTOT;

    uint hwv[16], lwv[16];
    #pragma unroll
    for (int t = 0; t < 16; t++) {
        float v0 = st[nl * 264 + jb + 2 * t];
        float v1 = st[nl * 264 + jb + 2 * t + 1];
        __nv_bfloat16 h0 = __float2bfloat16(v0);
        __nv_bfloat16 h1 = __float2bfloat16(v1);
        __nv_bfloat16 l0 = __float2bfloat16(v0 - __bfloat162float(h0));
        __nv_bfloat16 l1 = __float2bfloat16(v1 - __bfloat162float(h1));
        hwv[t] = (uint)__bfloat16_as_ushort(h0) | ((uint)__bfloat16_as_ushort(h1) << 16);
        lwv[t] = (uint)__bfloat16_as_ushort(l0) | ((uint)__bfloat16_as_ushort(l1) << 16);
    }
    uint4* p0 = (uint4*)(rowp + jb);            // hi
    uint4* p1 = (uint4*)(rowp + 256 + jb);      // B: lo,  A: hi
    uint4* p2 = (uint4*)(rowp + 512 + jb);      // B: hi,  A: lo
    #pragma unroll
    for (int t = 0; t < 4; t++) {
        uint4 hv = make_uint4(hwv[4*t], hwv[4*t+1], hwv[4*t+2], hwv[4*t+3]);
        uint4 lv = make_uint4(lwv[4*t], lwv[4*t+1], lwv[4*t+2], lwv[4*t+3]);
        p0[t] = hv;
        p1[t] = isB ? lv : hv;
        p2[t] = isB ? hv : lv;
    }
}

// ---------------------------------------------------------------------------
// K1: HMMA bf16 distance GEMM fused with per-token top-2.
// CTA tile 128x128, 128 threads = 4 warps (2m x 2n), warp tile 64x64.
// Each CTA processes TWO adjacent n-blocks with ONE continuous 24-stage
// cp.async pipeline (never drained); the nb=0 epilogue overlaps nb=1
// prefetch. 100KB smem -> 2 CTAs/SM so sibling CTAs hide each other's
// barriers. Grid (64 m-tiles, 32 n-pairs) = 2048 CTAs, ~6.9 waves.
// ---------------------------------------------------------------------------
__global__ void __launch_bounds__(128, 2)
k_mma() {
    extern __shared__ char smem[];
    const uint sb  = smem_u32(smem);
    const uint sA  = sb;                       // 3 x 16KB
    const uint sB  = sb + NPIPE * ABYTES;      // 3 x 16KB
    ull* sred = (ull*)(smem + SM_RED);         // 4KB, separate from tiles

    const int tid  = threadIdx.x;
    const int lane = tid & 31;
    const int wid  = tid >> 5;      // 0..3
    const int wm   = wid & 1;       // m warp (2): 64 rows each
    const int wn   = wid >> 1;      // n warp (2): 64 cols each

    const int m0   = blockIdx.x * MTILE;
    const int pair = blockIdx.y;                 // 0..31
    const int n0p  = pair * (2 * NTILE);

    const __nv_bfloat16* gA = g_A + (ull)m0 * KTOT;
    const __nv_bfloat16* gB = g_B + (ull)n0p * KTOT;

    // --- hoisted issue-side address components (tid-constant) ---
    const int ld_row = tid >> 3;           // 0..15
    const int ld_ch  = tid & 7;
    const uint ld_sw = (uint)((ld_ch ^ (ld_row & 7)) << 4);
    const uint dst_base = (uint)ld_row * 128u + ld_sw;
    const __nv_bfloat16* srcA0 = gA + (ull)ld_row * KTOT + ld_ch * 8;
    const __nv_bfloat16* srcB0 = gB + (ull)ld_row * KTOT + ld_ch * 8;

    // --- hoisted ldmatrix address components ---
    const int rowA = wm * 64 + (lane & 7) + ((lane >> 3) & 1) * 8;  // + i*16
    const int chA  = (lane >> 4);
    const int rowB = wn * 64 + (lane & 7) + ((lane >> 4) << 3);     // + nb*16
    const int chB  = (lane >> 3) & 1;
    uint colA[4], colB[4];
    #pragma unroll
    for (int ks = 0; ks < 4; ks++) {
        colA[ks] = (uint)(((ks * 2 + chA) ^ (rowA & 7)) << 4);
        colB[ks] = (uint)(((ks * 2 + chB) ^ (rowB & 7)) << 4);
    }
    uint rbaseA[4], rbaseB[4];
    #pragma unroll
    for (int i = 0; i < 4; i++) rbaseA[i] = (uint)(rowA + i * 16) * 128u;
    #pragma unroll
    for (int i = 0; i < 4; i++) rbaseB[i] = (uint)(rowB + i * 16) * 128u;

    // global-stage issuer: gs in [0,24), nb = gs/12, k-stage = gs%12
    auto issue = [&](int gs, int buf) {
        const int nb = (gs >= NSTAGES) ? 1 : 0;
        const int kb = (gs - nb * NSTAGES) * KS;
        const uint bufA = sA + (uint)buf * ABYTES;
        const uint bufB = sB + (uint)buf * BBYTES;
        const __nv_bfloat16* sa  = srcA0 + kb;
        const __nv_bfloat16* sbp = srcB0 + (ull)nb * NTILE * KTOT + kb;
        #pragma unroll
        for (int i = 0; i < 8; i++)
            CP16(bufA + dst_base + (uint)i * 2048u, sa + (ull)i * 16 * KTOT);
        #pragma unroll
        for (int i = 0; i < 8; i++)
            CP16(bufB + dst_base + (uint)i * 2048u, sbp + (ull)i * 16 * KTOT);
        CP_COMMIT();
    };

    issue(0, 0); issue(1, 1);

    float c[4][8][4];
    int buf = 0;

    for (int nb = 0; nb < 2; nb++) {
        #pragma unroll
        for (int i = 0; i < 4; i++)
            #pragma unroll
            for (int j = 0; j < 8; j++)
                #pragma unroll
                for (int r = 0; r < 4; r++) c[i][j][r] = 0.0f;

        for (int s = 0; s < NSTAGES; s++) {
            const int gs = nb * NSTAGES + s;
            if (gs < GSTAGES - 1) { CP_WAIT(1); } else { CP_WAIT(0); }
            __syncthreads();

            const uint bufA = sA + (uint)buf * ABYTES;
            const uint bufB = sB + (uint)buf * BBYTES;

            #pragma unroll
            for (int ks = 0; ks < 4; ks++) {
                uint a[4][4];
                #pragma unroll
                for (int i = 0; i < 4; i++)
                    LDSM4(a[i][0], a[i][1], a[i][2], a[i][3],
                          bufA + rbaseA[i] + colA[ks]);
                uint b[8][2];
                #pragma unroll
                for (int nbm = 0; nbm < 4; nbm++) {
                    uint r0, r1, r2, r3;
                    LDSM4(r0, r1, r2, r3, bufB + rbaseB[nbm] + colB[ks]);
                    b[nbm * 2][0] = r0;     b[nbm * 2][1] = r1;
                    b[nbm * 2 + 1][0] = r2; b[nbm * 2 + 1][1] = r3;
                }
                #pragma unroll
                for (int i = 0; i < 4; i++)
                    #pragma unroll
                    for (int j = 0; j < 8; j++)
                        MMA16816(c[i][j], a[i], b[j]);
            }
            if (gs + 2 < GSTAGES) {
                int nbuf = buf + 2; if (nbuf >= NPIPE) nbuf -= NPIPE;
                issue(gs + 2, nbuf);
            }
            if (++buf == NPIPE) buf = 0;
        }

        // ------- epilogue nb: dist + top-2 (overlaps nb=1 prefetch) ---------
        const int n0 = n0p + nb * NTILE;

        float e2v[8][2];
        #pragma unroll
        for (int j = 0; j < 8; j++)
            #pragma unroll
            for (int q = 0; q < 2; q++)
                e2v[j][q] = g_e2[n0 + wn * 64 + j * 8 + (lane & 3) * 2 + q];

        #pragma unroll
        for (int i = 0; i < 4; i++) {
            #pragma unroll
            for (int h = 0; h < 2; h++) {
                const int m_local = wm * 64 + i * 16 + (lane >> 2) + h * 8;
                const float sx2 = g_sx2[m0 + m_local];
                ull b1 = 0ull, b2 = 0ull;
                #pragma unroll
                for (int j = 0; j < 8; j++) {
                    #pragma unroll
                    for (int q = 0; q < 2; q++) {
                        float dot  = c[i][j][h * 2 + q];
                        float dist = (sx2 - 2.0f * dot) + e2v[j][q];
                        const int n = n0 + wn * 64 + j * 8 + (lane & 3) * 2 + q;
                        uint u = __float_as_uint(dist);
                        uint m = (u & 0x80000000u) ? ~u : (u | 0x80000000u);
                        ull key = ((ull)(~m) << 32) | (uint)(KCODES - 1 - n);
                        if (key > b1)      { b2 = b1; b1 = key; }
                        else if (key > b2) { b2 = key; }
                    }
                }
                #pragma unroll
                for (int sh = 1; sh <= 2; sh <<= 1) {
                    ull o1 = __shfl_xor_sync(0xffffffffu, b1, sh);
                    ull o2 = __shfl_xor_sync(0xffffffffu, b2, sh);
                    ull n1 = umax(b1, o1);
                    ull n2 = umax(umin(b1, o1), umax(b2, o2));
                    b1 = n1; b2 = n2;
                }
                if ((lane & 3) == 0) {
                    sred[(m_local * 2 + wn) * 2 + 0] = b1;
                    sred[(m_local * 2 + wn) * 2 + 1] = b2;
                }
            }
        }
        __syncthreads();
        {
            const int row = tid;   // 128 rows, 128 threads
            ull p1a = sred[(row * 2 + 0) * 2 + 0], p2a = sred[(row * 2 + 0) * 2 + 1];
            ull p1b = sred[(row * 2 + 1) * 2 + 0], p2b = sred[(row * 2 + 1) * 2 + 1];
            ull b1 = umax(p1a, p1b);
            ull b2 = umax(umin(p1a, p1b), umax(p2a, p2b));
            const int nblk = pair * 2 + nb;
            g_top1[(ull)(m0 + row) * NSPLITS + nblk] = b1;   // [token][split]
            g_top2[(ull)(m0 + row) * NSPLITS + nblk] = b2;
        }
        __syncthreads();   // sred readers done before next epilogue rewrites
    }
}

// ---------------------------------------------------------------------------
// K2a: warp-per-token split merge + near-tie exact fp32 fixup (lane-parallel)
// ---------------------------------------------------------------------------
__global__ void k_assign(const float* __restrict__ z, const float* __restrict__ E,
                         float* __restrict__ out) {
    const int gtid = blockIdx.x * 256 + threadIdx.x;
    const int n    = gtid >> 5;          // token = warp
    const int lane = gtid & 31;
    if (n >= NTOK) return;

    const ull* t1p = g_top1 + (ull)n * NSPLITS;
    const ull* t2p = g_top2 + (ull)n * NSPLITS;
    ull b1 = 0ull, b2 = 0ull;
    #pragma unroll
    for (int r = 0; r < 2; r++) {
        int s = lane + r * 32;
        ull t1 = t1p[s], t2 = t2p[s];
        if (t1 > b1)      { b2 = b1; b1 = t1; }
        else if (t1 > b2) { b2 = t1; }
        if (t2 > b2)      { b2 = t2; }
    }
    #pragma unroll
    for (int sh = 16; sh >= 1; sh >>= 1) {
        ull o1 = __shfl_xor_sync(0xffffffffu, b1, sh);
        ull o2 = __shfl_xor_sync(0xffffffffu, b2, sh);
        ull n1 = umax(b1, o1);
        ull n2 = umax(umin(b1, o1), umax(b2, o2));
        b1 = n1; b2 = n2;
    }

    int i1 = (KCODES - 1) - (int)(uint)(b1 & 0xffffffffu);
    int i2 = (KCODES - 1) - (int)(uint)(b2 & 0xffffffffu);
    uint m1 = ~(uint)(b1 >> 32), m2 = ~(uint)(b2 >> 32);
    float d1 = __uint_as_float((m1 & 0x80000000u) ? (m1 & 0x7fffffffu) : ~m1);
    float d2 = __uint_as_float((m2 & 0x80000000u) ? (m2 & 0x7fffffffu) : ~m2);

    int idx = i1;
    if (d2 - d1 < 2e-4f) {
        // exact fp32 re-score, lane-parallel (8 dims/lane), bucketed like ref
        int b = n >> 10, hw = n & 1023;
        const float* zp  = z + b * DD * HW + hw;
        const float* ep1 = E + i1;
        const float* ep2 = E + i2;
        float dot1 = 0.0f, dot2 = 0.0f;
        #pragma unroll
        for (int t = 0; t < 8; t++) {
            int d = t * 32 + lane;
            float zv = zp[d * HW];
            dot1 = fmaf(zv, ep1[d * KCODES], dot1);
            dot2 = fmaf(zv, ep2[d * KCODES], dot2);
        }
        #pragma unroll
        for (int sh = 16; sh >= 1; sh >>= 1) {
            dot1 += __shfl_xor_sync(0xffffffffu, dot1, sh);
            dot2 += __shfl_xor_sync(0xffffffffu, dot2, sh);
        }
        float sx2 = g_sx2[n];
        float e1  = (sx2 - 2.0f * dot1) + g_e2[i1];
        float e2x = (sx2 - 2.0f * dot2) + g_e2[i2];
        if (e2x < e1 || (e2x == e1 && i2 < i1)) idx = i2;
    }
    if (lane == 0) {
        g_idx[n] = idx;
        out[OUT_IDX + n] = (float)idx;
        atomicAdd(&out[OUT_CS + idx], 1.0f);
    }
}

// ---------------------------------------------------------------------------
// K2b: gather quantized (NCHW), scatter dw, accumulate loss
// ---------------------------------------------------------------------------
__global__ void k_scatter(const float* __restrict__ z, const float* __restrict__ E,
                          float* __restrict__ out) {
    int tx = threadIdx.x & 31;
    int ty = threadIdx.x >> 5;
    int hw = blockIdx.x * 32 + tx;
    int d  = blockIdx.y * 8 + ty;
    int b  = blockIdx.z;

    int n   = b * HW + hw;
    int idx = g_idx[n];
    float q  = E[d * KCODES + idx];
    int   zi = (b * DD + d) * HW + hw;
    float zv = z[zi];
    out[OUT_Q + zi] = q;
    float diff = q - zv;
    atomicAdd(&out[OUT_DW + d * KCODES + idx], zv);

    __shared__ float red[256];
    red[threadIdx.x] = diff * diff;
    __syncthreads();
    #pragma unroll
    for (int s = 128; s > 0; s >>= 1) {
        if (threadIdx.x < s) red[threadIdx.x] += red[threadIdx.x + s];
        __syncthreads();
    }
    if (threadIdx.x == 0) atomicAdd(&g_loss, (double)red[0]);
}

// ---------------------------------------------------------------------------
// K3: loss + perplexity
// ---------------------------------------------------------------------------
__global__ void k_final(float* __restrict__ out) {
    __shared__ float red[256];
    int t = threadIdx.x;
    float s = 0.0f;
    for (int k = t; k < KCODES; k += 256) {
        float p = out[OUT_CS + k] * (1.0f / 8192.0f);
        s += p * logf(p + 1e-10f);
    }
    red[t] = s;
    __syncthreads();
    #pragma unroll
    for (int st = 128; st > 0; st >>= 1) {
        if (t < st) red[t] += red[t + st];
        __syncthreads();
    }
    if (t == 0) {
        out[OUT_PERP] = expf(-red[0]);
        out[OUT_LOSS] = (float)(0.25 * g_loss / 2097152.0);
    }
}

// ---------------------------------------------------------------------------
extern "C" void kernel_launch(void* const* d_in, const int* in_sizes, int n_in,
                              void* d_out, int out_size) {
    const float* z = (const float*)d_in[0];         // [8,256,32,32]
    const float* E = (const float*)d_in[1];         // [256,8192]
    float* out = (float*)d_out;

    cudaFuncSetAttribute(k_mma, cudaFuncAttributeMaxDynamicSharedMemorySize,
                         SMEM_DYN);

    k_prep   <<< 512, 256 >>>(z, E, out);
    k_mma    <<< dim3(NTOK / MTILE, NSPLITS / 2), 128, SMEM_DYN >>>();
    k_assign <<< (NTOK * 32) / 256, 256 >>>(z, E, out);
    k_scatter<<< dim3(HW / 32, DD / 8, BATCH), 256 >>>(z, E, out);
    k_final  <<< 1, 256 >>>(out);
}